// round 1
// baseline (speedup 1.0000x reference)
#include <cuda_runtime.h>
#include <math.h>

#define Bsz 4
#define Ssz 2048
#define Dsz 768
#define Hsz 12
#define HDsz 64
#define BH (Bsz*Hsz)          // 48
#define MROWS (Bsz*Ssz)       // 8192
#define N_QKV (3*Dsz)         // 2304

// ---------------- scratch (no allocations allowed) ----------------
__device__ float g_Q[BH * Ssz * HDsz];   // [b,h,s,hd]
__device__ float g_K[BH * Ssz * HDsz];
__device__ float g_V[BH * Ssz * HDsz];
__device__ float g_attn[MROWS * Dsz];    // [b,s, h*64+hd]
__device__ float g_x[MROWS * Dsz];       // proj + bias + residual

// ---------------- QKV GEMM: context[8192,768] @ w_qkv[768,2304] ----------------
// 64x64 block tile, 256 threads, 4x4 micro-tile, BK=16.
__global__ void qkv_gemm_kernel(const float* __restrict__ A,
                                const float* __restrict__ Bw)
{
    __shared__ float As[16][65];   // transposed: As[k][m]
    __shared__ float Bs[16][64];   // Bs[k][n]

    const int tid = threadIdx.x;
    const int tx = tid & 15, ty = tid >> 4;
    const int m0 = blockIdx.y * 64;
    const int n0 = blockIdx.x * 64;

    float acc[4][4];
#pragma unroll
    for (int i = 0; i < 4; i++)
#pragma unroll
        for (int j = 0; j < 4; j++) acc[i][j] = 0.f;

    for (int k0 = 0; k0 < Dsz; k0 += 16) {
#pragma unroll
        for (int l = 0; l < 4; l++) {
            int e = tid + l * 256;
            int m = e >> 4, k = e & 15;
            As[k][m] = A[(m0 + m) * Dsz + k0 + k];
        }
#pragma unroll
        for (int l = 0; l < 4; l++) {
            int e = tid + l * 256;
            int k = e >> 6, n = e & 63;
            Bs[k][n] = Bw[(k0 + k) * N_QKV + n0 + n];
        }
        __syncthreads();
#pragma unroll
        for (int k = 0; k < 16; k++) {
            float a[4], b[4];
#pragma unroll
            for (int i = 0; i < 4; i++) a[i] = As[k][ty * 4 + i];
#pragma unroll
            for (int j = 0; j < 4; j++) b[j] = Bs[k][tx * 4 + j];
#pragma unroll
            for (int i = 0; i < 4; i++)
#pragma unroll
                for (int j = 0; j < 4; j++) acc[i][j] = fmaf(a[i], b[j], acc[i][j]);
        }
        __syncthreads();
    }

    // epilogue: scatter into g_Q/g_K/g_V [b,h,s,hd]. One 64-wide tile == one head.
    const int which = n0 / Dsz;            // 0:Q 1:K 2:V (tile never crosses)
    const int h = (n0 % Dsz) >> 6;         // constant over tile
    float* dst = (which == 0) ? g_Q : (which == 1) ? g_K : g_V;
#pragma unroll
    for (int i = 0; i < 4; i++) {
        int m = m0 + ty * 4 + i;
        int b = m >> 11;                   // /2048
        int s = m & 2047;
        float* row = dst + ((b * Hsz + h) * Ssz + s) * HDsz;
#pragma unroll
        for (int j = 0; j < 4; j++) row[tx * 4 + j] = acc[i][j];
    }
}

// ---------------- Flash attention: per (bh, q-tile of 64) ----------------
// dyn smem: Qs[64][65], KP[64][65] (K^T then P), Vs[64][64]
#define SM_QS 0
#define SM_KP (64*65)
#define SM_VS (64*65 + 64*65)
#define ATTN_SMEM_BYTES ((64*65 + 64*65 + 64*64) * 4)

__global__ void attn_kernel(const float* __restrict__ pad_mask)
{
    extern __shared__ float sm[];
    float* Qs = sm + SM_QS;
    float* KP = sm + SM_KP;
    float* Vs = sm + SM_VS;

    const int tid = threadIdx.x;
    const int tx = tid & 15, ty = tid >> 4;
    const int q0 = blockIdx.x * 64;
    const int bh = blockIdx.y;
    const int b = bh / Hsz;
    const int h = bh % Hsz;

    const float* Qg = g_Q + bh * Ssz * HDsz;
    const float* Kg = g_K + bh * Ssz * HDsz;
    const float* Vg = g_V + bh * Ssz * HDsz;
    const float* mk = pad_mask + b * Ssz;

    // load Q tile (64 x 64), padded stride 65
#pragma unroll
    for (int l = 0; l < 16; l++) {
        int e = tid + l * 256;
        int r = e >> 6, c = e & 63;
        Qs[r * 65 + c] = Qg[(q0 + r) * HDsz + c];
    }

    float mr[4], lr[4], O[4][4];
#pragma unroll
    for (int i = 0; i < 4; i++) {
        mr[i] = -1e30f; lr[i] = 0.f;
#pragma unroll
        for (int j = 0; j < 4; j++) O[i][j] = 0.f;
    }

    const float scale = 0.125f;   // 1/sqrt(64)

    for (int kt = 0; kt < Ssz / 64; kt++) {
        const int key0 = kt * 64;
        // load K^T and V tiles
#pragma unroll
        for (int l = 0; l < 16; l++) {
            int e = tid + l * 256;
            int r = e >> 6, c = e & 63;   // r = key, c = hd
            KP[c * 65 + r] = Kg[(key0 + r) * HDsz + c];
            Vs[r * 64 + c] = Vg[(key0 + r) * HDsz + c];
        }
        __syncthreads();

        // S = Q @ K^T   (4x4 per thread)
        float s4[4][4];
#pragma unroll
        for (int i = 0; i < 4; i++)
#pragma unroll
            for (int j = 0; j < 4; j++) s4[i][j] = 0.f;
#pragma unroll 16
        for (int k = 0; k < 64; k++) {
            float a[4], bb[4];
#pragma unroll
            for (int i = 0; i < 4; i++) a[i] = Qs[(ty * 4 + i) * 65 + k];
#pragma unroll
            for (int j = 0; j < 4; j++) bb[j] = KP[k * 65 + tx * 4 + j];
#pragma unroll
            for (int i = 0; i < 4; i++)
#pragma unroll
                for (int j = 0; j < 4; j++) s4[i][j] = fmaf(a[i], bb[j], s4[i][j]);
        }

        // scale + mask
        float mv[4];
#pragma unroll
        for (int j = 0; j < 4; j++) mv[j] = mk[key0 + tx * 4 + j];
#pragma unroll
        for (int i = 0; i < 4; i++)
#pragma unroll
            for (int j = 0; j < 4; j++) {
                float v = s4[i][j] * scale;
                s4[i][j] = v * mv[j] - (1.f - mv[j]) * 1e10f;
            }

        // online softmax (reduce across 16-lane groups)
        float p4[4][4];
#pragma unroll
        for (int i = 0; i < 4; i++) {
            float tmax = fmaxf(fmaxf(s4[i][0], s4[i][1]), fmaxf(s4[i][2], s4[i][3]));
#pragma unroll
            for (int off = 1; off < 16; off <<= 1)
                tmax = fmaxf(tmax, __shfl_xor_sync(0xffffffffu, tmax, off));
            float mnew = fmaxf(mr[i], tmax);
            float corr = __expf(mr[i] - mnew);
            float rsum = 0.f;
#pragma unroll
            for (int j = 0; j < 4; j++) {
                p4[i][j] = __expf(s4[i][j] - mnew);
                rsum += p4[i][j];
            }
#pragma unroll
            for (int off = 1; off < 16; off <<= 1)
                rsum += __shfl_xor_sync(0xffffffffu, rsum, off);
            lr[i] = lr[i] * corr + rsum;
            mr[i] = mnew;
#pragma unroll
            for (int j = 0; j < 4; j++) O[i][j] *= corr;
        }

        __syncthreads();           // everyone done reading K^T
        // store P into KP
#pragma unroll
        for (int i = 0; i < 4; i++)
#pragma unroll
            for (int j = 0; j < 4; j++)
                KP[(ty * 4 + i) * 65 + tx * 4 + j] = p4[i][j];
        __syncthreads();

        // O += P @ V
#pragma unroll 16
        for (int k = 0; k < 64; k++) {
            float pv[4], v[4];
#pragma unroll
            for (int i = 0; i < 4; i++) pv[i] = KP[(ty * 4 + i) * 65 + k];
#pragma unroll
            for (int j = 0; j < 4; j++) v[j] = Vs[k * 64 + tx * 4 + j];
#pragma unroll
            for (int i = 0; i < 4; i++)
#pragma unroll
                for (int j = 0; j < 4; j++) O[i][j] = fmaf(pv[i], v[j], O[i][j]);
        }
        __syncthreads();           // before next tile's loads
    }

    // epilogue -> g_attn [b, s, h*64+hd]
#pragma unroll
    for (int i = 0; i < 4; i++) {
        float inv = 1.f / lr[i];
        int s = q0 + ty * 4 + i;
        float* row = g_attn + (b * Ssz + s) * Dsz + h * HDsz;
#pragma unroll
        for (int j = 0; j < 4; j++) row[tx * 4 + j] = O[i][j] * inv;
    }
}

// ---------------- Proj GEMM: g_attn[8192,768] @ w_proj[768,768] + b + resid ----------------
__global__ void proj_gemm_kernel(const float* __restrict__ Bw,
                                 const float* __restrict__ bias,
                                 const float* __restrict__ resid)
{
    __shared__ float As[16][65];
    __shared__ float Bs[16][64];

    const int tid = threadIdx.x;
    const int tx = tid & 15, ty = tid >> 4;
    const int m0 = blockIdx.y * 64;
    const int n0 = blockIdx.x * 64;

    float acc[4][4];
#pragma unroll
    for (int i = 0; i < 4; i++)
#pragma unroll
        for (int j = 0; j < 4; j++) acc[i][j] = 0.f;

    for (int k0 = 0; k0 < Dsz; k0 += 16) {
#pragma unroll
        for (int l = 0; l < 4; l++) {
            int e = tid + l * 256;
            int m = e >> 4, k = e & 15;
            As[k][m] = g_attn[(m0 + m) * Dsz + k0 + k];
        }
#pragma unroll
        for (int l = 0; l < 4; l++) {
            int e = tid + l * 256;
            int k = e >> 6, n = e & 63;
            Bs[k][n] = Bw[(k0 + k) * Dsz + n0 + n];
        }
        __syncthreads();
#pragma unroll
        for (int k = 0; k < 16; k++) {
            float a[4], b[4];
#pragma unroll
            for (int i = 0; i < 4; i++) a[i] = As[k][ty * 4 + i];
#pragma unroll
            for (int j = 0; j < 4; j++) b[j] = Bs[k][tx * 4 + j];
#pragma unroll
            for (int i = 0; i < 4; i++)
#pragma unroll
                for (int j = 0; j < 4; j++) acc[i][j] = fmaf(a[i], b[j], acc[i][j]);
        }
        __syncthreads();
    }

#pragma unroll
    for (int i = 0; i < 4; i++) {
        int m = m0 + ty * 4 + i;
#pragma unroll
        for (int j = 0; j < 4; j++) {
            int n = n0 + tx * 4 + j;
            g_x[m * Dsz + n] = acc[i][j] + bias[n] + resid[m * Dsz + n];
        }
    }
}

// ---------------- LayerNorm over rows of 768 ----------------
__global__ void ln_kernel(const float* __restrict__ gamma,
                          const float* __restrict__ beta,
                          float* __restrict__ out)
{
    __shared__ float red[256];
    const int row = blockIdx.x;
    const int t = threadIdx.x;
    const float* xr = g_x + row * Dsz;

    float v[3];
    float s = 0.f;
#pragma unroll
    for (int i = 0; i < 3; i++) { v[i] = xr[t + i * 256]; s += v[i]; }
    red[t] = s; __syncthreads();
#pragma unroll
    for (int off = 128; off > 0; off >>= 1) {
        if (t < off) red[t] += red[t + off];
        __syncthreads();
    }
    float mean = red[0] * (1.f / 768.f);
    __syncthreads();

    float s2 = 0.f;
#pragma unroll
    for (int i = 0; i < 3; i++) { float d = v[i] - mean; s2 += d * d; }
    red[t] = s2; __syncthreads();
#pragma unroll
    for (int off = 128; off > 0; off >>= 1) {
        if (t < off) red[t] += red[t + off];
        __syncthreads();
    }
    float var = red[0] * (1.f / 768.f);
    float inv = rsqrtf(var + 1e-5f);

    float* orow = out + row * Dsz;
#pragma unroll
    for (int i = 0; i < 3; i++) {
        int c = t + i * 256;
        orow[c] = (v[i] - mean) * inv * gamma[c] + beta[c];
    }
}

// ---------------- launch ----------------
extern "C" void kernel_launch(void* const* d_in, const int* in_sizes, int n_in,
                              void* d_out, int out_size)
{
    const float* context  = (const float*)d_in[0];
    const float* pad_mask = (const float*)d_in[1];
    const float* w_qkv    = (const float*)d_in[2];
    const float* w_proj   = (const float*)d_in[3];
    const float* b_proj   = (const float*)d_in[4];
    const float* gamma    = (const float*)d_in[5];
    const float* beta     = (const float*)d_in[6];
    float* out = (float*)d_out;

    cudaFuncSetAttribute(attn_kernel, cudaFuncAttributeMaxDynamicSharedMemorySize,
                         ATTN_SMEM_BYTES);

    qkv_gemm_kernel<<<dim3(N_QKV / 64, MROWS / 64), 256>>>(context, w_qkv);
    attn_kernel<<<dim3(Ssz / 64, BH), 256, ATTN_SMEM_BYTES>>>(pad_mask);
    proj_gemm_kernel<<<dim3(Dsz / 64, MROWS / 64), 256>>>(w_proj, b_proj, context);
    ln_kernel<<<MROWS, 256>>>(gamma, beta, out);
}